// round 7
// baseline (speedup 1.0000x reference)
#include <cuda_runtime.h>

// LIF forward scan — round 7: 256-bit global accesses (Blackwell v8.f32).
// 8 neurons/thread -> each warp ld/st is 1KB (8 full lines), giving the DRAM
// controller longer same-direction bursts at the read/write-turnaround-limited
// operating point (5.62 TB/s plateau across R1-R6). Total traffic unchanged.
// tpb=64, 1024 blocks -> single balanced wave (R5's win preserved).

static constexpr int B = 32;
static constexpr int T = 64;
static constexpr int N = 16384;
static constexpr int N8 = N / 8;          // 2048 8-float lanes per row

__device__ __forceinline__ void ldg256(const float* p, float r[8]) {
    asm("ld.global.v8.f32 {%0,%1,%2,%3,%4,%5,%6,%7}, [%8];"
        : "=f"(r[0]), "=f"(r[1]), "=f"(r[2]), "=f"(r[3]),
          "=f"(r[4]), "=f"(r[5]), "=f"(r[6]), "=f"(r[7])
        : "l"(p));
}

__device__ __forceinline__ void stg256(float* p, const float r[8]) {
    asm volatile("st.global.v8.f32 [%8], {%0,%1,%2,%3,%4,%5,%6,%7};"
        :: "f"(r[0]), "f"(r[1]), "f"(r[2]), "f"(r[3]),
           "f"(r[4]), "f"(r[5]), "f"(r[6]), "f"(r[7]), "l"(p)
        : "memory");
}

__global__ __launch_bounds__(64) void lif_kernel(
    const float* __restrict__ x,          // [B, T, N]
    const float* __restrict__ thresh,     // [N]
    const float* __restrict__ taux,       // [N]
    float* __restrict__ spikes,           // [B, T, N]
    float* __restrict__ mems)             // [B, T, N]
{
    const int idx = blockIdx.x * blockDim.x + threadIdx.x;  // [0, B*N8)
    const int n8 = idx & (N8 - 1);
    const int b  = idx >> 11;             // idx / N8

    float th[8], tx[8];
    ldg256(thresh + n8 * 8, th);
    ldg256(taux   + n8 * 8, tx);

    float sig[8], mem[8];
    #pragma unroll
    for (int i = 0; i < 8; ++i) {
        sig[i] = 1.0f / (1.0f + __expf(-tx[i]));
        mem[i] = 0.0f;
    }

    const size_t base = (size_t)b * T * N + (size_t)n8 * 8;
    const float* xp = x + base;
    float* sp = spikes + base;
    float* mp = mems + base;

    #pragma unroll 8
    for (int t = 0; t < T; ++t) {
        float xv[8];
        ldg256(xp + (size_t)t * N, xv);

        float s[8];
        #pragma unroll
        for (int i = 0; i < 8; ++i) {
            // leaky integration: mem += sig * (x - mem)
            mem[i] = fmaf(sig[i], xv[i] - mem[i], mem[i]);
            // Heaviside fire (>= threshold), hard reset
            s[i] = (mem[i] >= th[i]) ? 1.0f : 0.0f;
            mem[i] = (s[i] != 0.0f) ? 0.0f : mem[i];
        }

        stg256(sp + (size_t)t * N, s);
        stg256(mp + (size_t)t * N, mem);   // post-reset membrane
    }
}

extern "C" void kernel_launch(void* const* d_in, const int* in_sizes, int n_in,
                              void* d_out, int out_size)
{
    const float* x    = (const float*)d_in[0];
    const float* th   = (const float*)d_in[1];
    const float* taux = (const float*)d_in[2];

    float* spikes = (float*)d_out;
    float* mems   = (float*)d_out + (size_t)B * T * N;

    const int total = B * N8;             // 65536 threads
    const int tpb = 64;                   // 1024 blocks, single balanced wave
    lif_kernel<<<total / tpb, tpb>>>(x, th, taux, spikes, mems);
}

// round 8
// speedup vs baseline: 1.0509x; 1.0509x over previous
#include <cuda_runtime.h>

// LIF forward scan — FINAL (R5 configuration, ceiling-confirmed).
// x: [B=32, T=64, N=16384] f32; thresh, tau_x: [N] f32
// out: spikes [B,T,N] f32 then mems [B,T,N] f32 (post-reset membrane).
//
// Roofline: 384 MB mandatory traffic at the measured mixed 1:2 read/write
// HBM3e ceiling (~5.6 TB/s, 70% of spec) -> ~62 us floor. This kernel hits
// 61.76 us / DRAM 71.0%. Validated non-levers: occupancy (R2), forced MLP
// (R3), streaming cache hints (R4: -9us), unroll depth (R6), 256-bit
// accesses (R7). The one real lever was wave balance: 1024 CTAs x 128
// threads = 6.92 CTAs/SM, whole grid resident in a single wave, ~1% skew.

static constexpr int B = 32;
static constexpr int T = 64;
static constexpr int N = 16384;
static constexpr int N4 = N / 4;          // 4096 float4 lanes per row

__global__ __launch_bounds__(128) void lif_kernel(
    const float4* __restrict__ x,         // [B, T, N4]
    const float4* __restrict__ thresh4,   // [N4]
    const float4* __restrict__ taux4,     // [N4]
    float4* __restrict__ spikes,          // [B, T, N4]
    float4* __restrict__ mems)            // [B, T, N4]
{
    const int idx = blockIdx.x * blockDim.x + threadIdx.x;  // [0, B*N4)
    const int n4 = idx & (N4 - 1);
    const int b  = idx >> 12;             // idx / N4

    const float4 th = thresh4[n4];
    const float4 tx = taux4[n4];

    // sigmoid(tau_x), constant over timesteps
    float4 sig;
    sig.x = 1.0f / (1.0f + __expf(-tx.x));
    sig.y = 1.0f / (1.0f + __expf(-tx.y));
    sig.z = 1.0f / (1.0f + __expf(-tx.z));
    sig.w = 1.0f / (1.0f + __expf(-tx.w));

    float4 mem = make_float4(0.f, 0.f, 0.f, 0.f);

    const size_t base = (size_t)b * T * N4 + n4;
    const float4* xp = x + base;
    float4* sp = spikes + base;
    float4* mp = mems + base;

    #pragma unroll 8
    for (int t = 0; t < T; ++t) {
        const float4 xv = xp[(size_t)t * N4];

        // leaky integration: mem += sig * (x - mem)
        mem.x = fmaf(sig.x, xv.x - mem.x, mem.x);
        mem.y = fmaf(sig.y, xv.y - mem.y, mem.y);
        mem.z = fmaf(sig.z, xv.z - mem.z, mem.z);
        mem.w = fmaf(sig.w, xv.w - mem.w, mem.w);

        // Heaviside fire (>= threshold) and hard reset
        float4 s;
        s.x = (mem.x >= th.x) ? 1.0f : 0.0f;
        s.y = (mem.y >= th.y) ? 1.0f : 0.0f;
        s.z = (mem.z >= th.z) ? 1.0f : 0.0f;
        s.w = (mem.w >= th.w) ? 1.0f : 0.0f;

        mem.x = (s.x != 0.0f) ? 0.0f : mem.x;
        mem.y = (s.y != 0.0f) ? 0.0f : mem.y;
        mem.z = (s.z != 0.0f) ? 0.0f : mem.z;
        mem.w = (s.w != 0.0f) ? 0.0f : mem.w;

        sp[(size_t)t * N4] = s;
        mp[(size_t)t * N4] = mem;  // post-reset membrane
    }
}

extern "C" void kernel_launch(void* const* d_in, const int* in_sizes, int n_in,
                              void* d_out, int out_size)
{
    const float4* x    = (const float4*)d_in[0];
    const float4* th   = (const float4*)d_in[1];
    const float4* taux = (const float4*)d_in[2];

    float4* spikes = (float4*)d_out;
    float4* mems   = (float4*)((float*)d_out + (size_t)B * T * N);

    const int total = B * N4;             // 131072 threads
    const int tpb = 128;                  // 1024 blocks, single balanced wave
    lif_kernel<<<total / tpb, tpb>>>(x, th, taux, spikes, mems);
}